// round 17
// baseline (speedup 1.0000x reference)
#include <cuda_runtime.h>
#include <cuda_bf16.h>
#include <stdint.h>

#define BB 512
#define TT 256
#define HH 256
#define HORZ 22
#define RPB 4          // batch rows per CTA
#define NTH 256        // one thread per hidden column
#define NCTA (BB / RPB)

#define SCL  16.0f
#define ISCL 0.0625f

// dynamic smem layout (bytes)
#define OFF_WZR 0          // u32 [128kp][256col] : e4m3x4 (uz,ur)k0 | (uz,ur)k1<<16, x16 = 131072
#define OFF_UH  131072     // u32 [64kq][256col]  : e4m3x4 uh[4kq..4kq+3] x16 = 65536
#define OFF_HT  196608     // f16 [256k][4r] = 2048      (h0,h1,h2,h3)
#define OFF_RHT 198656     // u32 [128kp][4r] = 2048     k-paired (rh[2kp],rh[2kp+1]) per row
#define OFF_XST 200704     // f32 [256t][4r] = 4096      (reused post-loop: f32 h [4r][256col])
#define OFF_WV  204800     // f32 [8][256]   = 8192      (reused post-loop: f32 hid [4r][256col])
#define OFF_HTS 212992     // f16 [256k][4r] = 2048      swapped copy (h1,h0,h3,h2)
#define SMEM_BYTES 215040

__device__ __forceinline__ float ftanha(float x) {
    float y; asm("tanh.approx.f32 %0, %1;" : "=f"(y) : "f"(x)); return y;
}
__device__ __forceinline__ float fsig(float x) {
    return fmaf(0.5f, ftanha(0.5f * x), 0.5f);
}
__device__ __forceinline__ uint32_t s2u(const void* p) {
    return (uint32_t)__cvta_generic_to_shared(p);
}
__device__ __forceinline__ void hfma2(uint32_t& d, uint32_t a, uint32_t b) {
    asm("fma.rn.f16x2 %0, %1, %2, %0;" : "+r"(d) : "r"(a), "r"(b));
}
// split u32 of e4m3x4 into two f16x2 words
__device__ __forceinline__ void f8x4_to_2h2(uint32_t w, uint32_t& lo, uint32_t& hi) {
    asm("{.reg .b16 l,h;\n\t"
        "mov.b32 {l,h}, %2;\n\t"
        "cvt.rn.f16x2.e4m3x2 %0, l;\n\t"
        "cvt.rn.f16x2.e4m3x2 %1, h;}"
        : "=r"(lo), "=r"(hi) : "r"(w));
}
__device__ __forceinline__ float2 h2f(uint32_t p) {   // f16x2 -> (f32 lo, f32 hi)
    float2 f;
    asm("{.reg .b16 l,h; mov.b32 {l,h}, %2; cvt.f32.f16 %0, l; cvt.f32.f16 %1, h;}"
        : "=f"(f.x), "=f"(f.y) : "r"(p));
    return f;
}
__device__ __forceinline__ uint32_t f2h2(float lo, float hi) {   // pack (lo,hi) f16x2
    uint32_t d; asm("cvt.rn.f16x2.f32 %0, %1, %2;" : "=r"(d) : "f"(hi), "f"(lo)); return d;
}
__device__ __forceinline__ uint16_t f2h1(float v) {      // f32 -> f16 bits
    uint16_t d; asm("cvt.rn.f16.f32 %0, %1;" : "=h"(d) : "f"(v)); return d;
}
__device__ __forceinline__ uint16_t f2e8x2(float lo, float hi) { // pack e4m3x2
    uint16_t d; asm("cvt.rn.satfinite.e4m3x2.f32 %0, %1, %2;" : "=h"(d) : "f"(hi), "f"(lo));
    return d;
}
__device__ __forceinline__ void sts32(uint32_t a, uint32_t v) {
    asm volatile("st.shared.b32 [%0], %1;" :: "r"(a), "r"(v));
}
__device__ __forceinline__ void sts16(uint32_t a, uint16_t v) {
    asm volatile("st.shared.u16 [%0], %1;" :: "r"(a), "h"(v));
}

extern "C" __global__ __launch_bounds__(NTH, 1)
void garch_gru_fused(const float* __restrict__ x,
                     const float* __restrict__ Wzw, const float* __restrict__ Wzb,
                     const float* __restrict__ Uzw, const float* __restrict__ Uzb,
                     const float* __restrict__ Wrw, const float* __restrict__ Wrb,
                     const float* __restrict__ Urw, const float* __restrict__ Urb,
                     const float* __restrict__ Whw, const float* __restrict__ Whb,
                     const float* __restrict__ Uhw, const float* __restrict__ Uhb,
                     const float* __restrict__ Wgw, const float* __restrict__ Wgb,
                     const float* __restrict__ omega_raw, const float* __restrict__ alpha_raw,
                     const float* __restrict__ beta_raw,  const float* __restrict__ gamma_p,
                     const float* __restrict__ fc1w, const float* __restrict__ fc1b,
                     const float* __restrict__ fc2w, const float* __restrict__ fc2b,
                     float* __restrict__ out, int sig_off)
{
    extern __shared__ char smem[];
    float* xsT = (float*)(smem + OFF_XST);
    float* wv  = (float*)(smem + OFF_WV);

    const int tid = threadIdx.x;
    const int col = tid;                       // hidden column owned
    const int rbase = (int)blockIdx.x * RPB;   // batch rows of this CTA

    const uint32_t smem_u = s2u(smem);
    const uint32_t wzr2_base = smem_u + OFF_WZR + col * 4;  // + kp*1024
    const uint32_t uh2_base  = smem_u + OFF_UH  + col * 4;  // + kq*1024
    const uint32_t ht_base   = smem_u + OFF_HT;             // + k*8 (v4 = 2 k)
    const uint32_t hts_base  = smem_u + OFF_HTS;            // swapped copy
    const uint32_t rht_base  = smem_u + OFF_RHT;            // + kp*16 (v4 = 4 rows, k-paired)
    const uint32_t ht_own    = smem_u + OFF_HT  + col * 8;
    const uint32_t hts_own   = smem_u + OFF_HTS + col * 8;
    // k-paired rh store: word (col>>1), half (col&1), row stride 4B
    const uint32_t rht_own16 = smem_u + OFF_RHT + ((col >> 1) << 4) + ((col & 1) << 1);
    const uint32_t xs_base   = smem_u + OFF_XST;

    // ---- preamble: convert weights to packed e4m3 words (scaled x16) ----
    #pragma unroll 4
    for (int kp = 0; kp < HH / 2; kp++) {
        const int k0 = 2 * kp;
        const uint16_t p0 = f2e8x2(Uzw[k0 * HH + col] * SCL, Urw[k0 * HH + col] * SCL);
        const uint16_t p1 = f2e8x2(Uzw[(k0+1) * HH + col] * SCL, Urw[(k0+1) * HH + col] * SCL);
        sts32(wzr2_base + kp * 1024, (uint32_t)p0 | ((uint32_t)p1 << 16));
    }
    #pragma unroll 4
    for (int kq = 0; kq < HH / 4; kq++) {
        const int k0 = 4 * kq;
        const uint16_t p0 = f2e8x2(Uhw[k0 * HH + col] * SCL, Uhw[(k0+1) * HH + col] * SCL);
        const uint16_t p1 = f2e8x2(Uhw[(k0+2) * HH + col] * SCL, Uhw[(k0+3) * HH + col] * SCL);
        sts32(uh2_base + kq * 1024, (uint32_t)p0 | ((uint32_t)p1 << 16));
    }
    {   // per-column scalars (fp32)
        wv[0*HH+col] = Wzw[col];
        wv[1*HH+col] = Wzb[col] + Uzb[col];
        wv[2*HH+col] = Wrw[col];
        wv[3*HH+col] = Wrb[col] + Urb[col];
        wv[4*HH+col] = Whw[col];
        wv[5*HH+col] = Whb[col] + Uhb[col];
        wv[6*HH+col] = Wgw[col];
        wv[7*HH+col] = Wgb[col];
    }
    // x tile (fp32, exact: feeds GARCH)
    for (int idx = tid; idx < RPB * TT; idx += NTH) {
        int r = idx >> 8, t = idx & (TT - 1);
        xsT[t * RPB + r] = x[(rbase + r) * TT + t];
    }
    // zero h (both copies)
    asm volatile("st.shared.v2.b32 [%0], {%1,%1};" :: "r"(ht_own),  "r"(0u));
    asm volatile("st.shared.v2.b32 [%0], {%1,%1};" :: "r"(hts_own), "r"(0u));
    __syncthreads();

    // ---- per-thread constants ----
    const float wzc = wv[0*HH+col], bzc = wv[1*HH+col];
    const float wrc = wv[2*HH+col], brc = wv[3*HH+col];
    const float whc = wv[4*HH+col], bhc = wv[5*HH+col];
    const float wgc = wv[6*HH+col], wgbc= wv[7*HH+col];
    const float gamma = gamma_p[0];

    // GARCH scalar params (exact fp32; replicated on all threads)
    const float orw = omega_raw[0];
    const float om = ((orw > 20.0f) ? orw : log1pf(expf(orw))) + 1e-6f;
    const float av = 1.0f / (1.0f + expf(-alpha_raw[0]));
    const float bv = (1.0f / (1.0f + expf(-beta_raw[0]))) * (1.0f - av * 0.99f);
    float4 es = make_float4(1e-6f, 1e-6f, 1e-6f, 1e-6f);
    float4 ss = es;

    // own h kept in fp32 registers
    float h0 = 0.0f, h1 = 0.0f, h2 = 0.0f, h3 = 0.0f;

    for (int t = 0; t < TT; t++) {
        float4 xv;
        asm("ld.shared.v4.f32 {%0,%1,%2,%3}, [%4];"
            : "=f"(xv.x), "=f"(xv.y), "=f"(xv.z), "=f"(xv.w)
            : "r"(xs_base + t * 16));

        // hoisted loop-independent work: x-projections, GARCH update, gt
        const float xz0 = fmaf(xv.x, wzc, bzc), xz1 = fmaf(xv.y, wzc, bzc);
        const float xz2 = fmaf(xv.z, wzc, bzc), xz3 = fmaf(xv.w, wzc, bzc);
        const float xr0 = fmaf(xv.x, wrc, brc), xr1 = fmaf(xv.y, wrc, brc);
        const float xr2 = fmaf(xv.z, wrc, brc), xr3 = fmaf(xv.w, wrc, brc);
        const float xh0 = fmaf(xv.x, whc, bhc), xh1 = fmaf(xv.y, whc, bhc);
        const float xh2 = fmaf(xv.z, whc, bhc), xh3 = fmaf(xv.w, whc, bhc);
        float4 g;
        g.x = fmaf(av, es.x, fmaf(bv, ss.x, om));
        g.y = fmaf(av, es.y, fmaf(bv, ss.y, om));
        g.z = fmaf(av, es.z, fmaf(bv, ss.z, om));
        g.w = fmaf(av, es.w, fmaf(bv, ss.w, om));
        es = make_float4(xv.x*xv.x, xv.y*xv.y, xv.z*xv.z, xv.w*xv.w);
        ss = g;
        const float gt0 = fmaf(g.x, wgc, wgbc), gt1 = fmaf(g.y, wgc, wgbc);
        const float gt2 = fmaf(g.z, wgc, wgbc), gt3 = fmaf(g.w, wgc, wgbc);

        // ---- phase A: gate-mixed accumulators, NO dup instructions ----
        // P0=(z0,r1), P1=(z1,r0), P2=(z2,r3), P3=(z3,r2)
        uint32_t P0 = 0u, P1 = 0u, P2 = 0u, P3 = 0u;
        #pragma unroll 8
        for (int kp = 0; kp < HH / 2; kp++) {
            uint32_t g01a, g23a, g01b, g23b;       // (h0,h1),(h2,h3) for k0,k1
            asm("ld.shared.v4.b32 {%0,%1,%2,%3}, [%4];"
                : "=r"(g01a), "=r"(g23a), "=r"(g01b), "=r"(g23b)
                : "r"(ht_base + kp * 16));
            uint32_t s01a, s23a, s01b, s23b;       // (h1,h0),(h3,h2) for k0,k1
            asm("ld.shared.v4.b32 {%0,%1,%2,%3}, [%4];"
                : "=r"(s01a), "=r"(s23a), "=r"(s01b), "=r"(s23b)
                : "r"(hts_base + kp * 16));
            uint32_t w2;
            asm("ld.shared.b32 %0, [%1];" : "=r"(w2) : "r"(wzr2_base + kp * 1024));
            uint32_t wA, wB;
            f8x4_to_2h2(w2, wA, wB);               // (uz,ur) for k0 and k1 — used directly
            hfma2(P0, g01a, wA); hfma2(P1, s01a, wA);
            hfma2(P2, g23a, wA); hfma2(P3, s23a, wA);
            hfma2(P0, g01b, wB); hfma2(P1, s01b, wB);
            hfma2(P2, g23b, wB); hfma2(P3, s23b, wB);
        }
        const float2 q0 = h2f(P0), q1 = h2f(P1), q2 = h2f(P2), q3 = h2f(P3);
        // q0=(z0,r1) q1=(z1,r0) q2=(z2,r3) q3=(z3,r2)
        const float z0 = fsig(fmaf(q0.x, ISCL, xz0));
        const float z1 = fsig(fmaf(q1.x, ISCL, xz1));
        const float z2v= fsig(fmaf(q2.x, ISCL, xz2));
        const float z3 = fsig(fmaf(q3.x, ISCL, xz3));
        const float rh0 = fsig(fmaf(q1.y, ISCL, xr0)) * h0;
        const float rh1 = fsig(fmaf(q0.y, ISCL, xr1)) * h1;
        const float rh2 = fsig(fmaf(q3.y, ISCL, xr2)) * h2;
        const float rh3 = fsig(fmaf(q2.y, ISCL, xr3)) * h3;
        // k-paired rh store: u16 halves of word (col>>1), per row
        sts16(rht_own16 + 0,  f2h1(rh0));
        sts16(rht_own16 + 4,  f2h1(rh1));
        sts16(rht_own16 + 8,  f2h1(rh2));
        sts16(rht_own16 + 12, f2h1(rh3));
        const float zh0 = z0 * h0, zh1 = z1 * h1, zh2 = z2v * h2, zh3 = z3 * h3;
        __syncthreads();   // r*h tile complete

        // ---- phase B: per-row (even,odd) accumulators, NO dup instructions ----
        uint32_t B0 = 0u, B1 = 0u, B2 = 0u, B3 = 0u;
        #pragma unroll 8
        for (int kq = 0; kq < HH / 4; kq++) {
            uint32_t wa0, wa1, wa2, wa3;           // kp0 = 2kq: (rh_k0,rh_k1) rows 0..3
            asm("ld.shared.v4.b32 {%0,%1,%2,%3}, [%4];"
                : "=r"(wa0), "=r"(wa1), "=r"(wa2), "=r"(wa3)
                : "r"(rht_base + kq * 32));
            uint32_t wb0, wb1, wb2, wb3;           // kp1 = 2kq+1: (rh_k2,rh_k3) rows 0..3
            asm("ld.shared.v4.b32 {%0,%1,%2,%3}, [%4];"
                : "=r"(wb0), "=r"(wb1), "=r"(wb2), "=r"(wb3)
                : "r"(rht_base + kq * 32 + 16));
            uint32_t u2;
            asm("ld.shared.b32 %0, [%1];" : "=r"(u2) : "r"(uh2_base + kq * 1024));
            uint32_t uA, uB;
            f8x4_to_2h2(u2, uA, uB);               // (uh_k0,uh_k1), (uh_k2,uh_k3) — direct
            hfma2(B0, wa0, uA); hfma2(B1, wa1, uA);
            hfma2(B2, wa2, uA); hfma2(B3, wa3, uA);
            hfma2(B0, wb0, uB); hfma2(B1, wb1, uB);
            hfma2(B2, wb2, uB); hfma2(B3, wb3, uB);
        }
        const float2 c0 = h2f(B0), c1 = h2f(B1), c2 = h2f(B2), c3 = h2f(B3);
        const float t0 = ftanha(fmaf(c0.x + c0.y, ISCL, xh0));
        const float t1 = ftanha(fmaf(c1.x + c1.y, ISCL, xh1));
        const float t2 = ftanha(fmaf(c2.x + c2.y, ISCL, xh2));
        const float t3 = ftanha(fmaf(c3.x + c3.y, ISCL, xh3));
        h0 = ftanha(fmaf(gamma, gt0, fmaf(-z0, t0, t0) + zh0));
        h1 = ftanha(fmaf(gamma, gt1, fmaf(-z1, t1, t1) + zh1));
        h2 = ftanha(fmaf(gamma, gt2, fmaf(-z2v, t2, t2) + zh2));
        h3 = ftanha(fmaf(gamma, gt3, fmaf(-z3, t3, t3) + zh3));
        {   // store both h copies: (h0,h1),(h2,h3) and swapped (h1,h0),(h3,h2)
            const uint32_t p01 = f2h2(h0, h1), p23 = f2h2(h2, h3);
            const uint32_t s01 = f2h2(h1, h0), s23 = f2h2(h3, h2);
            asm volatile("st.shared.v2.b32 [%0], {%1,%2};"
                         :: "r"(ht_own), "r"(p01), "r"(p23));
            asm volatile("st.shared.v2.b32 [%0], {%1,%2};"
                         :: "r"(hts_own), "r"(s01), "r"(s23));
        }
        __syncthreads();   // h tile complete -> next step
    }

    // ================= fused head =================
    // sigma_sq output (exact fp32 path)
    if (tid == 0) {
        out[sig_off + rbase + 0] = ss.x;
        out[sig_off + rbase + 1] = ss.y;
        out[sig_off + rbase + 2] = ss.z;
        out[sig_off + rbase + 3] = ss.w;
    }
    // share exact fp32 h via SMEM (reuse xsT area): layout [r][col], conflict-free
    float* hsh = xsT;                      // 4 * 256 * 4B = 4096 B
    hsh[0 * HH + col] = h0;
    hsh[1 * HH + col] = h1;
    hsh[2 * HH + col] = h2;
    hsh[3 * HH + col] = h3;
    __syncthreads();

    // fc1: hid[r][col] = relu(fc1b[col] + sum_k h[r][k] * fc1w[k][col])
    float a0 = fc1b[col], a1 = a0, a2 = a0, a3 = a0;
    #pragma unroll 4
    for (int k = 0; k < HH; k++) {
        const float w = fc1w[k * HH + col];   // coalesced; L2-broadcast across CTAs
        a0 = fmaf(hsh[0 * HH + k], w, a0);
        a1 = fmaf(hsh[1 * HH + k], w, a1);
        a2 = fmaf(hsh[2 * HH + k], w, a2);
        a3 = fmaf(hsh[3 * HH + k], w, a3);
    }
    float* hid = wv;                       // reuse WV area: [r][col] = 4096 B
    hid[0 * HH + col] = fmaxf(a0, 0.0f);
    hid[1 * HH + col] = fmaxf(a1, 0.0f);
    hid[2 * HH + col] = fmaxf(a2, 0.0f);
    hid[3 * HH + col] = fmaxf(a3, 0.0f);
    __syncthreads();

    // fc2 + softplus + vol: 88 threads (r = tid/22, o = tid%22)
    if (tid < RPB * HORZ) {
        const int r = tid / HORZ, o = tid - r * HORZ;
        float u = fc2b[o];
        #pragma unroll 4
        for (int j = 0; j < HH; j++) u = fmaf(hid[r * HH + j], fc2w[j * HORZ + o], u);
        const float sp = (u > 20.0f) ? u : log1pf(expf(u));
        const float ssq = (r == 0) ? ss.x : (r == 1) ? ss.y : (r == 2) ? ss.z : ss.w;
        const float vb = sqrtf(ssq + 1e-8f);
        float v = vb * (1.0f + sp);
        v = fminf(fmaxf(v, 0.01f), 10.0f);
        out[(rbase + r) * HORZ + o] = v;
    }
}

extern "C" void kernel_launch(void* const* d_in, const int* in_sizes, int n_in,
                              void* d_out, int out_size) {
    const float* x    = (const float*)d_in[0];
    const float* Wzw  = (const float*)d_in[1];
    const float* Wzb  = (const float*)d_in[2];
    const float* Uzw  = (const float*)d_in[3];
    const float* Uzb  = (const float*)d_in[4];
    const float* Wrw  = (const float*)d_in[5];
    const float* Wrb  = (const float*)d_in[6];
    const float* Urw  = (const float*)d_in[7];
    const float* Urb  = (const float*)d_in[8];
    const float* Whw  = (const float*)d_in[9];
    const float* Whb  = (const float*)d_in[10];
    const float* Uhw  = (const float*)d_in[11];
    const float* Uhb  = (const float*)d_in[12];
    const float* Wgw  = (const float*)d_in[13];
    const float* Wgb  = (const float*)d_in[14];
    const float* omr  = (const float*)d_in[15];
    const float* alr  = (const float*)d_in[16];
    const float* ber  = (const float*)d_in[17];
    const float* gam  = (const float*)d_in[18];
    const float* fc1w = (const float*)d_in[19];
    const float* fc1b = (const float*)d_in[20];
    const float* fc2w = (const float*)d_in[21];
    const float* fc2b = (const float*)d_in[22];
    float* out = (float*)d_out;
    const int sig_off = out_size - BB;   // vol[B,HOR] then sigma_sq[B]

    cudaFuncSetAttribute(garch_gru_fused,
                         cudaFuncAttributeMaxDynamicSharedMemorySize, SMEM_BYTES);
    garch_gru_fused<<<NCTA, NTH, SMEM_BYTES>>>(
        x, Wzw, Wzb, Uzw, Uzb, Wrw, Wrb, Urw, Urb, Whw, Whb, Uhw, Uhb, Wgw, Wgb,
        omr, alr, ber, gam, fc1w, fc1b, fc2w, fc2b, out, sig_off);
}